// round 1
// baseline (speedup 1.0000x reference)
#include <cuda_runtime.h>
#include <math.h>

#define BB 2
#define SS 2048
#define DIMD 512
#define HEADS 4
#define DH 128
#define CHUNK 16
#define NCHUNK 128
#define BH 8
#define DH2 16384
#define MAX_LR 0.01f
#define EPSV 1e-6f

// ---------------- scratch (no allocation allowed) ----------------
__device__ float g_xnorm[BB*SS*DIMD];                 // 8 MB
__device__ float g_k[BH*NCHUNK*CHUNK*DH];             // 8 MB
__device__ float g_v[BH*NCHUNK*CHUNK*DH];             // 8 MB
__device__ float g_lr[BH*NCHUNK*CHUNK];
__device__ float g_mom[BH*NCHUNK];
__device__ float g_dec[BH*NCHUNK];

__device__ __forceinline__ float sigf(float x) { return 1.f / (1.f + __expf(-x)); }

// ---------------- K1: RMSNorm + per-token lr ----------------
// grid 4096 (tokens), block 128
__global__ void k_rmsnorm(const float* __restrict__ seq,
                          const float* __restrict__ scale,
                          const float* __restrict__ Wstep) {
    int tok = blockIdx.x;
    int tid = threadIdx.x;
    int lane = tid & 31, warp = tid >> 5;
    __shared__ float red[4];
    __shared__ float redp[4][4];

    float4 v = ((const float4*)(seq + (size_t)tok * DIMD))[tid];
    float ss = v.x*v.x + v.y*v.y + v.z*v.z + v.w*v.w;
#pragma unroll
    for (int o = 16; o; o >>= 1) ss += __shfl_xor_sync(0xffffffffu, ss, o);
    if (lane == 0) red[warp] = ss;
    __syncthreads();
    float tot = red[0] + red[1] + red[2] + red[3];
    float inv = rsqrtf(tot * (1.f / DIMD) + EPSV);

    float4 sc = ((const float4*)scale)[tid];
    float4 xn = make_float4(v.x*inv*sc.x, v.y*inv*sc.y, v.z*inv*sc.z, v.w*inv*sc.w);
    ((float4*)(g_xnorm + (size_t)tok * DIMD))[tid] = xn;

    // lr partials: Wstep is [DIM][HEADS]
    int d0 = tid * 4;
    float4 wa = ((const float4*)Wstep)[d0 + 0];
    float4 wb = ((const float4*)Wstep)[d0 + 1];
    float4 wc = ((const float4*)Wstep)[d0 + 2];
    float4 wd = ((const float4*)Wstep)[d0 + 3];
    float p0 = xn.x*wa.x + xn.y*wb.x + xn.z*wc.x + xn.w*wd.x;
    float p1 = xn.x*wa.y + xn.y*wb.y + xn.z*wc.y + xn.w*wd.y;
    float p2 = xn.x*wa.z + xn.y*wb.z + xn.z*wc.z + xn.w*wd.z;
    float p3 = xn.x*wa.w + xn.y*wb.w + xn.z*wc.w + xn.w*wd.w;
#pragma unroll
    for (int o = 16; o; o >>= 1) {
        p0 += __shfl_xor_sync(0xffffffffu, p0, o);
        p1 += __shfl_xor_sync(0xffffffffu, p1, o);
        p2 += __shfl_xor_sync(0xffffffffu, p2, o);
        p3 += __shfl_xor_sync(0xffffffffu, p3, o);
    }
    if (lane == 0) { redp[warp][0] = p0; redp[warp][1] = p1; redp[warp][2] = p2; redp[warp][3] = p3; }
    __syncthreads();
    if (tid < 4) {
        float p = redp[0][tid] + redp[1][tid] + redp[2][tid] + redp[3][tid];
        float lrv = MAX_LR * sigf(p);
        int b = tok / SS, s = tok % SS;
        int t = s / CHUNK, c = s % CHUNK;
        g_lr[(((b * HEADS + tid) * NCHUNK + t) * CHUNK) + c] = lrv;
    }
}

// ---------------- K2: chunk means -> mom/dec ----------------
// grid B*NCHUNK = 256, block 128
__global__ void k_chunkstats(const float* __restrict__ Wmom,
                             const float* __restrict__ Wdec) {
    int blk = blockIdx.x;
    int b = blk / NCHUNK, t = blk % NCHUNK;
    int tid = threadIdx.x;
    int lane = tid & 31, warp = tid >> 5;
    __shared__ float redp[4][8];

    int d0 = tid * 4;
    const float* xb = g_xnorm + ((size_t)(b * SS + t * CHUNK)) * DIMD;
    float4 m = make_float4(0.f, 0.f, 0.f, 0.f);
#pragma unroll
    for (int c = 0; c < CHUNK; c++) {
        float4 v = *(const float4*)(xb + (size_t)c * DIMD + d0);
        m.x += v.x; m.y += v.y; m.z += v.z; m.w += v.w;
    }
    m.x *= (1.f/CHUNK); m.y *= (1.f/CHUNK); m.z *= (1.f/CHUNK); m.w *= (1.f/CHUNK);

    float4 ma = ((const float4*)Wmom)[d0 + 0];
    float4 mb = ((const float4*)Wmom)[d0 + 1];
    float4 mc = ((const float4*)Wmom)[d0 + 2];
    float4 md = ((const float4*)Wmom)[d0 + 3];
    float4 da = ((const float4*)Wdec)[d0 + 0];
    float4 db = ((const float4*)Wdec)[d0 + 1];
    float4 dc = ((const float4*)Wdec)[d0 + 2];
    float4 dd = ((const float4*)Wdec)[d0 + 3];

    float p[8];
    p[0] = m.x*ma.x + m.y*mb.x + m.z*mc.x + m.w*md.x;
    p[1] = m.x*ma.y + m.y*mb.y + m.z*mc.y + m.w*md.y;
    p[2] = m.x*ma.z + m.y*mb.z + m.z*mc.z + m.w*md.z;
    p[3] = m.x*ma.w + m.y*mb.w + m.z*mc.w + m.w*md.w;
    p[4] = m.x*da.x + m.y*db.x + m.z*dc.x + m.w*dd.x;
    p[5] = m.x*da.y + m.y*db.y + m.z*dc.y + m.w*dd.y;
    p[6] = m.x*da.z + m.y*db.z + m.z*dc.z + m.w*dd.z;
    p[7] = m.x*da.w + m.y*db.w + m.z*dc.w + m.w*dd.w;
#pragma unroll
    for (int i = 0; i < 8; i++) {
#pragma unroll
        for (int o = 16; o; o >>= 1) p[i] += __shfl_xor_sync(0xffffffffu, p[i], o);
    }
    if (lane == 0) {
#pragma unroll
        for (int i = 0; i < 8; i++) redp[warp][i] = p[i];
    }
    __syncthreads();
    if (tid < 8) {
        float s = redp[0][tid] + redp[1][tid] + redp[2][tid] + redp[3][tid];
        float sv = sigf(s);
        int h = tid & 3;
        if (tid < 4) g_mom[(b * HEADS + h) * NCHUNK + t] = sv;
        else         g_dec[(b * HEADS + h) * NCHUNK + t] = sv;
    }
}

// ---------------- K3: kv projection ----------------
// grid 256 (b, t), block 256; each thread: 4 cols x 16 rows
__global__ void k_kvproj(const float* __restrict__ Wkv) {
    __shared__ float xs[CHUNK * DIMD];   // 32 KB
    int blk = blockIdx.x;
    int b = blk / NCHUNK, t = blk % NCHUNK;
    int tid = threadIdx.x;

    const float4* src = (const float4*)(g_xnorm + ((size_t)(b * SS + t * CHUNK)) * DIMD);
#pragma unroll
    for (int i = tid; i < CHUNK * DIMD / 4; i += 256) ((float4*)xs)[i] = src[i];
    __syncthreads();

    int col = tid * 4;
    float4 acc[CHUNK];
#pragma unroll
    for (int c = 0; c < CHUNK; c++) acc[c] = make_float4(0.f, 0.f, 0.f, 0.f);

#pragma unroll 4
    for (int d = 0; d < DIMD; d++) {
        float4 w = *(const float4*)(Wkv + (size_t)d * 1024 + col);
#pragma unroll
        for (int c = 0; c < CHUNK; c++) {
            float xv = xs[c * DIMD + d];
            acc[c].x += xv * w.x; acc[c].y += xv * w.y;
            acc[c].z += xv * w.z; acc[c].w += xv * w.w;
        }
    }

    int isv = (col >= 512);
    int col2 = col - isv * 512;
    int h = col2 >> 7, j = col2 & 127;
    float* dst = (isv ? g_v : g_k) + ((size_t)((b * HEADS + h) * NCHUNK + t)) * (CHUNK * DH) + j;
#pragma unroll
    for (int c = 0; c < CHUNK; c++)
        *(float4*)(dst + c * DH) = acc[c];
}

// ---------------- K4: per-chunk gradients ----------------
// grid 1024 (bh*128 + t), block 256, dyn smem 231488 B
#define W1T_PAD 132
__global__ void __launch_bounds__(256, 1)
k_grad(const float* __restrict__ w0g_all, const float* __restrict__ w1g_all,
       float* __restrict__ out) {
    extern __shared__ float sm[];
    float* w0s  = sm;                    // 16384
    float* w1s  = w0s + 16384;           // 16384
    float* w1ts = w1s + 16384;           // 128*132
    float* ks   = w1ts + 128 * W1T_PAD;  // 2048
    float* vs   = ks + 2048;             // 2048 (becomes G)
    float* hs   = vs + 2048;             // 2048 (becomes dh)
    float* as_  = hs + 2048;             // 2048
    float* lrs  = as_ + 2048;            // 16

    int bh = blockIdx.x >> 7;
    int t  = blockIdx.x & 127;
    int tid = threadIdx.x;

    const float* w0g = w0g_all + (size_t)bh * DH2;
    const float* w1g = w1g_all + (size_t)bh * DH2;
    for (int i = tid; i < DH2; i += 256) {
        w0s[i] = w0g[i];
        float wv = w1g[i];
        w1s[i] = wv;
        w1ts[(i & 127) * W1T_PAD + (i >> 7)] = wv;
    }
    const float* kg = g_k + ((size_t)(bh * NCHUNK + t)) * (CHUNK * DH);
    const float* vg = g_v + ((size_t)(bh * NCHUNK + t)) * (CHUNK * DH);
    for (int i = tid; i < CHUNK * DH; i += 256) { ks[i] = kg[i]; vs[i] = vg[i]; }
    if (tid < CHUNK) lrs[tid] = g_lr[(bh * NCHUNK + t) * CHUNK + tid];
    __syncthreads();

    int tx = tid & 31;     // j-group: j0 = tx*4
    int ty = tid >> 5;     // c-group: c0 = ty*2
    int c0 = ty * 2;
    int j0 = tx * 4;

    // ---- GEMM A: h = k @ w0, a = silu(h) ----
    {
        float4 a0 = make_float4(0,0,0,0), a1 = make_float4(0,0,0,0);
#pragma unroll 4
        for (int d = 0; d < DH; d++) {
            float k0 = ks[c0 * DH + d];
            float k1 = ks[c0 * DH + DH + d];
            float4 w = *(float4*)&w0s[d * DH + j0];
            a0.x += k0*w.x; a0.y += k0*w.y; a0.z += k0*w.z; a0.w += k0*w.w;
            a1.x += k1*w.x; a1.y += k1*w.y; a1.z += k1*w.z; a1.w += k1*w.w;
        }
        *(float4*)&hs[c0 * DH + j0] = a0;
        *(float4*)&hs[c0 * DH + DH + j0] = a1;
        float4 s0v = make_float4(a0.x*sigf(a0.x), a0.y*sigf(a0.y), a0.z*sigf(a0.z), a0.w*sigf(a0.w));
        float4 s1v = make_float4(a1.x*sigf(a1.x), a1.y*sigf(a1.y), a1.z*sigf(a1.z), a1.w*sigf(a1.w));
        *(float4*)&as_[c0 * DH + j0] = s0v;
        *(float4*)&as_[c0 * DH + DH + j0] = s1v;
    }
    __syncthreads();

    // ---- GEMM B: pred = a @ w1; G = 2*lr*(pred - v)/DH (into vs) ----
    {
        float4 a0 = make_float4(0,0,0,0), a1 = make_float4(0,0,0,0);
#pragma unroll 4
        for (int d = 0; d < DH; d++) {
            float x0 = as_[c0 * DH + d];
            float x1 = as_[c0 * DH + DH + d];
            float4 w = *(float4*)&w1s[d * DH + j0];
            a0.x += x0*w.x; a0.y += x0*w.y; a0.z += x0*w.z; a0.w += x0*w.w;
            a1.x += x1*w.x; a1.y += x1*w.y; a1.z += x1*w.z; a1.w += x1*w.w;
        }
        float f0 = 2.f * lrs[c0] * (1.f / DH);
        float f1 = 2.f * lrs[c0 + 1] * (1.f / DH);
        float4 v0 = *(float4*)&vs[c0 * DH + j0];
        float4 v1 = *(float4*)&vs[c0 * DH + DH + j0];
        float4 G0 = make_float4(f0*(a0.x - v0.x), f0*(a0.y - v0.y), f0*(a0.z - v0.z), f0*(a0.w - v0.w));
        float4 G1 = make_float4(f1*(a1.x - v1.x), f1*(a1.y - v1.y), f1*(a1.z - v1.z), f1*(a1.w - v1.w));
        *(float4*)&vs[c0 * DH + j0] = G0;
        *(float4*)&vs[c0 * DH + DH + j0] = G1;
    }
    __syncthreads();

    int tx2 = tid & 15;    // d2-group: 8 cols
    int ty2 = tid >> 4;    // d1-group: 8 rows
    int d1b = ty2 * 8;
    int d2b = tx2 * 8;

    // ---- GEMM G1: g1 = a^T @ G; write s1 = -g1 ----
    {
        float acc[8][8];
#pragma unroll
        for (int i = 0; i < 8; i++)
#pragma unroll
            for (int j = 0; j < 8; j++) acc[i][j] = 0.f;
#pragma unroll
        for (int c = 0; c < CHUNK; c++) {
            float4 aa = *(float4*)&as_[c * DH + d1b];
            float4 ab = *(float4*)&as_[c * DH + d1b + 4];
            float4 ga = *(float4*)&vs[c * DH + d2b];
            float4 gb = *(float4*)&vs[c * DH + d2b + 4];
            float av[8] = {aa.x, aa.y, aa.z, aa.w, ab.x, ab.y, ab.z, ab.w};
            float gv[8] = {ga.x, ga.y, ga.z, ga.w, gb.x, gb.y, gb.z, gb.w};
#pragma unroll
            for (int i = 0; i < 8; i++)
#pragma unroll
                for (int j = 0; j < 8; j++) acc[i][j] += av[i] * gv[j];
        }
        float* o1 = out + ((size_t)((BH + bh) * NCHUNK + t)) * DH2;
#pragma unroll
        for (int i = 0; i < 8; i++) {
            float4 r0 = make_float4(-acc[i][0], -acc[i][1], -acc[i][2], -acc[i][3]);
            float4 r1 = make_float4(-acc[i][4], -acc[i][5], -acc[i][6], -acc[i][7]);
            *(float4*)(o1 + (size_t)(d1b + i) * DH + d2b) = r0;
            *(float4*)(o1 + (size_t)(d1b + i) * DH + d2b + 4) = r1;
        }
    }

    // ---- GEMM C: dA = G @ w1^T; dh = dA * silu'(h) (into hs) ----
    {
        float4 a0 = make_float4(0,0,0,0), a1 = make_float4(0,0,0,0);
#pragma unroll 4
        for (int d = 0; d < DH; d++) {
            float gg0 = vs[c0 * DH + d];
            float gg1 = vs[c0 * DH + DH + d];
            float4 w = *(float4*)&w1ts[d * W1T_PAD + j0];
            a0.x += gg0*w.x; a0.y += gg0*w.y; a0.z += gg0*w.z; a0.w += gg0*w.w;
            a1.x += gg1*w.x; a1.y += gg1*w.y; a1.z += gg1*w.z; a1.w += gg1*w.w;
        }
        float4 h0 = *(float4*)&hs[c0 * DH + j0];
        float4 h1 = *(float4*)&hs[c0 * DH + DH + j0];
        float sg;
        sg = sigf(h0.x); a0.x *= sg * (1.f + h0.x * (1.f - sg));
        sg = sigf(h0.y); a0.y *= sg * (1.f + h0.y * (1.f - sg));
        sg = sigf(h0.z); a0.z *= sg * (1.f + h0.z * (1.f - sg));
        sg = sigf(h0.w); a0.w *= sg * (1.f + h0.w * (1.f - sg));
        sg = sigf(h1.x); a1.x *= sg * (1.f + h1.x * (1.f - sg));
        sg = sigf(h1.y); a1.y *= sg * (1.f + h1.y * (1.f - sg));
        sg = sigf(h1.z); a1.z *= sg * (1.f + h1.z * (1.f - sg));
        sg = sigf(h1.w); a1.w *= sg * (1.f + h1.w * (1.f - sg));
        __syncthreads();   // make sure everyone finished reading hs (GEMM C reads own idx only, but be safe before overwrite pattern below)
        *(float4*)&hs[c0 * DH + j0] = a0;
        *(float4*)&hs[c0 * DH + DH + j0] = a1;
    }
    __syncthreads();

    // ---- GEMM G0: g0 = k^T @ dh; write s0 = -g0 ----
    {
        float acc[8][8];
#pragma unroll
        for (int i = 0; i < 8; i++)
#pragma unroll
            for (int j = 0; j < 8; j++) acc[i][j] = 0.f;
#pragma unroll
        for (int c = 0; c < CHUNK; c++) {
            float4 aa = *(float4*)&ks[c * DH + d1b];
            float4 ab = *(float4*)&ks[c * DH + d1b + 4];
            float4 ga = *(float4*)&hs[c * DH + d2b];
            float4 gb = *(float4*)&hs[c * DH + d2b + 4];
            float av[8] = {aa.x, aa.y, aa.z, aa.w, ab.x, ab.y, ab.z, ab.w};
            float gv[8] = {ga.x, ga.y, ga.z, ga.w, gb.x, gb.y, gb.z, gb.w};
#pragma unroll
            for (int i = 0; i < 8; i++)
#pragma unroll
                for (int j = 0; j < 8; j++) acc[i][j] += av[i] * gv[j];
        }
        float* o0 = out + ((size_t)(bh * NCHUNK + t)) * DH2;
#pragma unroll
        for (int i = 0; i < 8; i++) {
            float4 r0 = make_float4(-acc[i][0], -acc[i][1], -acc[i][2], -acc[i][3]);
            float4 r1 = make_float4(-acc[i][4], -acc[i][5], -acc[i][6], -acc[i][7]);
            *(float4*)(o0 + (size_t)(d1b + i) * DH + d2b) = r0;
            *(float4*)(o0 + (size_t)(d1b + i) * DH + d2b + 4) = r1;
        }
    }
}

// ---------------- K5: fused momentum + decay scan (in place) ----------------
// grid 1024, block 256
__global__ void k_scan(float* __restrict__ out) {
    __shared__ float moms[NCHUNK], decs[NCHUNK];
    int blk = blockIdx.x;
    int sbh = blk >> 6;        // 0..15 = s*8 + bh
    int eb  = blk & 63;
    int bh  = sbh & 7;
    int tid = threadIdx.x;
    if (tid < NCHUNK) {
        moms[tid] = g_mom[bh * NCHUNK + tid];
        decs[tid] = 1.f - g_dec[bh * NCHUNK + tid];
    }
    __syncthreads();
    size_t base = (size_t)sbh * NCHUNK * DH2 + (size_t)eb * 256 + tid;
    float m = 0.f, u = 0.f;
#pragma unroll 4
    for (int t = 0; t < NCHUNK; t++) {
        size_t idx = base + (size_t)t * DH2;
        float sv = out[idx];
        m = moms[t] * m + sv;
        u = decs[t] * u + m;
        out[idx] = u;
    }
}

// ---------------- launch ----------------
extern "C" void kernel_launch(void* const* d_in, const int* in_sizes, int n_in,
                              void* d_out, int out_size) {
    const float* seq   = (const float*)d_in[0];
    const float* scale = (const float*)d_in[1];
    const float* Wkv   = (const float*)d_in[2];
    const float* Wstep = (const float*)d_in[3];
    const float* Wmom  = (const float*)d_in[4];
    const float* Wdec  = (const float*)d_in[5];
    const float* w0    = (const float*)d_in[6];
    const float* w1    = (const float*)d_in[7];
    float* out = (float*)d_out;

    const int GRAD_SMEM = (16384 + 16384 + 128 * W1T_PAD + 4 * 2048 + 16) * 4;
    cudaFuncSetAttribute(k_grad, cudaFuncAttributeMaxDynamicSharedMemorySize, GRAD_SMEM);

    k_rmsnorm<<<BB * SS, 128>>>(seq, scale, Wstep);
    k_chunkstats<<<BB * NCHUNK, 128>>>(Wmom, Wdec);
    k_kvproj<<<BB * NCHUNK, 256>>>(Wkv);
    k_grad<<<BH * NCHUNK, 256, GRAD_SMEM>>>(w0, w1, out);
    k_scan<<<1024, 256>>>(out);
}

// round 2
// speedup vs baseline: 1.3040x; 1.3040x over previous
#include <cuda_runtime.h>
#include <math.h>

#define BB 2
#define SS 2048
#define DIMD 512
#define HEADS 4
#define DH 128
#define CHUNK 16
#define NCHUNK 128
#define BH 8
#define DH2 16384
#define MAX_LR 0.01f
#define EPSV 1e-6f

// ---------------- scratch ----------------
__device__ float g_xnorm[BB*SS*DIMD];                 // 8 MB
__device__ float g_k[BH*NCHUNK*CHUNK*DH];             // 8 MB  (layout == [b][h][s][j])
__device__ float g_v[BH*NCHUNK*CHUNK*DH];             // 8 MB
__device__ float g_lr[BH*NCHUNK*CHUNK];
__device__ float g_mom[BH*NCHUNK];
__device__ float g_dec[BH*NCHUNK];

__device__ __forceinline__ float sigf(float x) { return 1.f / (1.f + __expf(-x)); }

// ------- packed f32x2 helpers (FFMA2 path, sm_103a) -------
__device__ __forceinline__ unsigned long long fma2(unsigned long long a,
                                                   unsigned long long b,
                                                   unsigned long long c) {
    unsigned long long d;
    asm("fma.rn.f32x2 %0, %1, %2, %3;" : "=l"(d) : "l"(a), "l"(b), "l"(c));
    return d;
}
__device__ __forceinline__ unsigned long long dup2(float x) {
    unsigned long long d;
    unsigned int xi = __float_as_uint(x);
    asm("mov.b64 %0, {%1, %1};" : "=l"(d) : "r"(xi));
    return d;
}
__device__ __forceinline__ float2 unpk2(unsigned long long v) {
    unsigned int lo, hi;
    asm("mov.b64 {%0, %1}, %2;" : "=r"(lo), "=r"(hi) : "l"(v));
    return make_float2(__uint_as_float(lo), __uint_as_float(hi));
}

// ---------------- K1: RMSNorm + per-token lr ----------------
__global__ void k_rmsnorm(const float* __restrict__ seq,
                          const float* __restrict__ scale,
                          const float* __restrict__ Wstep) {
    int tok = blockIdx.x;
    int tid = threadIdx.x;
    int lane = tid & 31, warp = tid >> 5;
    __shared__ float red[4];
    __shared__ float redp[4][4];

    float4 v = ((const float4*)(seq + (size_t)tok * DIMD))[tid];
    float ss = v.x*v.x + v.y*v.y + v.z*v.z + v.w*v.w;
#pragma unroll
    for (int o = 16; o; o >>= 1) ss += __shfl_xor_sync(0xffffffffu, ss, o);
    if (lane == 0) red[warp] = ss;
    __syncthreads();
    float tot = red[0] + red[1] + red[2] + red[3];
    float inv = rsqrtf(tot * (1.f / DIMD) + EPSV);

    float4 sc = ((const float4*)scale)[tid];
    float4 xn = make_float4(v.x*inv*sc.x, v.y*inv*sc.y, v.z*inv*sc.z, v.w*inv*sc.w);
    ((float4*)(g_xnorm + (size_t)tok * DIMD))[tid] = xn;

    int d0 = tid * 4;
    float4 wa = ((const float4*)Wstep)[d0 + 0];
    float4 wb = ((const float4*)Wstep)[d0 + 1];
    float4 wc = ((const float4*)Wstep)[d0 + 2];
    float4 wd = ((const float4*)Wstep)[d0 + 3];
    float p0 = xn.x*wa.x + xn.y*wb.x + xn.z*wc.x + xn.w*wd.x;
    float p1 = xn.x*wa.y + xn.y*wb.y + xn.z*wc.y + xn.w*wd.y;
    float p2 = xn.x*wa.z + xn.y*wb.z + xn.z*wc.z + xn.w*wd.z;
    float p3 = xn.x*wa.w + xn.y*wb.w + xn.z*wc.w + xn.w*wd.w;
#pragma unroll
    for (int o = 16; o; o >>= 1) {
        p0 += __shfl_xor_sync(0xffffffffu, p0, o);
        p1 += __shfl_xor_sync(0xffffffffu, p1, o);
        p2 += __shfl_xor_sync(0xffffffffu, p2, o);
        p3 += __shfl_xor_sync(0xffffffffu, p3, o);
    }
    if (lane == 0) { redp[warp][0] = p0; redp[warp][1] = p1; redp[warp][2] = p2; redp[warp][3] = p3; }
    __syncthreads();
    if (tid < 4) {
        float p = redp[0][tid] + redp[1][tid] + redp[2][tid] + redp[3][tid];
        float lrv = MAX_LR * sigf(p);
        int b = tok / SS, s = tok % SS;
        int t = s / CHUNK, c = s % CHUNK;
        g_lr[(((b * HEADS + tid) * NCHUNK + t) * CHUNK) + c] = lrv;
    }
}

// ---------------- K2: chunk means -> mom/dec ----------------
__global__ void k_chunkstats(const float* __restrict__ Wmom,
                             const float* __restrict__ Wdec) {
    int blk = blockIdx.x;
    int b = blk / NCHUNK, t = blk % NCHUNK;
    int tid = threadIdx.x;
    int lane = tid & 31, warp = tid >> 5;
    __shared__ float redp[4][8];

    int d0 = tid * 4;
    const float* xb = g_xnorm + ((size_t)(b * SS + t * CHUNK)) * DIMD;
    float4 m = make_float4(0.f, 0.f, 0.f, 0.f);
#pragma unroll
    for (int c = 0; c < CHUNK; c++) {
        float4 v = *(const float4*)(xb + (size_t)c * DIMD + d0);
        m.x += v.x; m.y += v.y; m.z += v.z; m.w += v.w;
    }
    m.x *= (1.f/CHUNK); m.y *= (1.f/CHUNK); m.z *= (1.f/CHUNK); m.w *= (1.f/CHUNK);

    float4 ma = ((const float4*)Wmom)[d0 + 0];
    float4 mb = ((const float4*)Wmom)[d0 + 1];
    float4 mc = ((const float4*)Wmom)[d0 + 2];
    float4 md = ((const float4*)Wmom)[d0 + 3];
    float4 da = ((const float4*)Wdec)[d0 + 0];
    float4 db = ((const float4*)Wdec)[d0 + 1];
    float4 dc = ((const float4*)Wdec)[d0 + 2];
    float4 dd = ((const float4*)Wdec)[d0 + 3];

    float p[8];
    p[0] = m.x*ma.x + m.y*mb.x + m.z*mc.x + m.w*md.x;
    p[1] = m.x*ma.y + m.y*mb.y + m.z*mc.y + m.w*md.y;
    p[2] = m.x*ma.z + m.y*mb.z + m.z*mc.z + m.w*md.z;
    p[3] = m.x*ma.w + m.y*mb.w + m.z*mc.w + m.w*md.w;
    p[4] = m.x*da.x + m.y*db.x + m.z*dc.x + m.w*dd.x;
    p[5] = m.x*da.y + m.y*db.y + m.z*dc.y + m.w*dd.y;
    p[6] = m.x*da.z + m.y*db.z + m.z*dc.z + m.w*dd.z;
    p[7] = m.x*da.w + m.y*db.w + m.z*dc.w + m.w*dd.w;
#pragma unroll
    for (int i = 0; i < 8; i++) {
#pragma unroll
        for (int o = 16; o; o >>= 1) p[i] += __shfl_xor_sync(0xffffffffu, p[i], o);
    }
    if (lane == 0) {
#pragma unroll
        for (int i = 0; i < 8; i++) redp[warp][i] = p[i];
    }
    __syncthreads();
    if (tid < 8) {
        float s = redp[0][tid] + redp[1][tid] + redp[2][tid] + redp[3][tid];
        float sv = sigf(s);
        int h = tid & 3;
        if (tid < 4) g_mom[(b * HEADS + h) * NCHUNK + t] = sv;
        else         g_dec[(b * HEADS + h) * NCHUNK + t] = sv;
    }
}

// ---------------- K3: kv projection (tiled, f32x2) ----------------
// grid 512: (cgp 0..3) * 128 + rg(0..127).  CTA: 32 tokens x 256 cols.
// 256 threads: rs = tid>>6 (8-row group), cg = tid&63 (4-col group).
#define KV_ROWS 32
__global__ void __launch_bounds__(256, 2) k_kvproj(const float* __restrict__ Wkv) {
    extern __shared__ float xs[];   // 32 * 512 floats = 64 KB
    int rg  = blockIdx.x & 127;
    int cgp = blockIdx.x >> 7;
    int tid = threadIdx.x;

    const float4* src = (const float4*)(g_xnorm + (size_t)rg * KV_ROWS * DIMD);
#pragma unroll
    for (int i = tid; i < KV_ROWS * DIMD / 4; i += 256) ((float4*)xs)[i] = src[i];
    __syncthreads();

    int rs = tid >> 6;        // 0..3
    int cg = tid & 63;        // 0..63
    int r0 = rs * 8;
    int col = cgp * 256 + cg * 4;

    unsigned long long acc[8][2];
#pragma unroll
    for (int r = 0; r < 8; r++) { acc[r][0] = 0ull; acc[r][1] = 0ull; }

    const float* wbase = Wkv + col;
#pragma unroll 2
    for (int dt = 0; dt < DIMD; dt += 4) {
        float4 xv[8];
#pragma unroll
        for (int r = 0; r < 8; r++) xv[r] = *(const float4*)&xs[(r0 + r) * DIMD + dt];
#pragma unroll
        for (int dd = 0; dd < 4; dd++) {
            ulonglong2 wl = *(const ulonglong2*)(wbase + (size_t)(dt + dd) * 1024);
#pragma unroll
            for (int r = 0; r < 8; r++) {
                float xc = (dd == 0) ? xv[r].x : (dd == 1) ? xv[r].y : (dd == 2) ? xv[r].z : xv[r].w;
                unsigned long long kk = dup2(xc);
                acc[r][0] = fma2(kk, wl.x, acc[r][0]);
                acc[r][1] = fma2(kk, wl.y, acc[r][1]);
            }
        }
    }

    int isv = (col >= 512);
    int c2 = col - isv * 512;
    int h = c2 >> 7, j = c2 & 127;
    float* base = (isv ? g_v : g_k);
#pragma unroll
    for (int r = 0; r < 8; r++) {
        int tg = rg * KV_ROWS + r0 + r;           // global token
        int b = tg >> 11, s = tg & 2047;
        float* dst = base + ((size_t)((b * HEADS + h) * SS + s)) * DH + j;
        *(ulonglong2*)dst = make_ulonglong2(acc[r][0], acc[r][1]);
    }
}

// ---------------- K4: per-chunk gradients (512 threads, f32x2) ----------------
#define W1T_PAD 132
__global__ void __launch_bounds__(512, 1)
k_grad(const float* __restrict__ w0g_all, const float* __restrict__ w1g_all,
       float* __restrict__ out) {
    extern __shared__ float sm[];
    float* w0s  = sm;                    // 16384
    float* w1s  = w0s + 16384;           // 16384
    float* w1ts = w1s + 16384;           // 128*132
    float* ks   = w1ts + 128 * W1T_PAD;  // 2048
    float* vs   = ks + 2048;             // 2048 (becomes Gn)
    float* hs   = vs + 2048;             // 2048 (becomes dhn)
    float* as_  = hs + 2048;             // 2048
    float* lrs  = as_ + 2048;            // 16

    int bh = blockIdx.x >> 7;
    int t  = blockIdx.x & 127;
    int tid = threadIdx.x;

    const float* w0g = w0g_all + (size_t)bh * DH2;
    const float* w1g = w1g_all + (size_t)bh * DH2;
    for (int i = tid; i < DH2; i += 512) {
        w0s[i] = w0g[i];
        float wv = w1g[i];
        w1s[i] = wv;
        w1ts[(i & 127) * W1T_PAD + (i >> 7)] = wv;
    }
    const float* kg = g_k + ((size_t)(bh * NCHUNK + t)) * (CHUNK * DH);
    const float* vg = g_v + ((size_t)(bh * NCHUNK + t)) * (CHUNK * DH);
    for (int i = tid; i < CHUNK * DH; i += 512) { ks[i] = kg[i]; vs[i] = vg[i]; }
    if (tid < CHUNK) lrs[tid] = g_lr[(bh * NCHUNK + t) * CHUNK + tid];
    __syncthreads();

    int c  = tid >> 5;          // 0..15 (one chunk row per thread)
    int tx = tid & 31;
    int j0 = tx * 4;

    // ---- GEMM A: h = k @ w0 ; a = silu(h) ----
    {
        unsigned long long a0 = 0ull, a1 = 0ull;
#pragma unroll 4
        for (int dt = 0; dt < DH; dt += 4) {
            float4 kx = *(const float4*)&ks[c * DH + dt];
#pragma unroll
            for (int dd = 0; dd < 4; dd++) {
                float kc = (dd == 0) ? kx.x : (dd == 1) ? kx.y : (dd == 2) ? kx.z : kx.w;
                unsigned long long kk = dup2(kc);
                ulonglong2 wl = *(const ulonglong2*)&w0s[(dt + dd) * DH + j0];
                a0 = fma2(kk, wl.x, a0);
                a1 = fma2(kk, wl.y, a1);
            }
        }
        *(ulonglong2*)&hs[c * DH + j0] = make_ulonglong2(a0, a1);
        float2 h01 = unpk2(a0), h23 = unpk2(a1);
        float4 av = make_float4(h01.x * sigf(h01.x), h01.y * sigf(h01.y),
                                h23.x * sigf(h23.x), h23.y * sigf(h23.y));
        *(float4*)&as_[c * DH + j0] = av;
    }
    __syncthreads();

    // ---- GEMM B: pred = a @ w1 ; Gn = f*(v - pred)  (into vs) ----
    {
        unsigned long long a0 = 0ull, a1 = 0ull;
#pragma unroll 4
        for (int dt = 0; dt < DH; dt += 4) {
            float4 ax = *(const float4*)&as_[c * DH + dt];
#pragma unroll
            for (int dd = 0; dd < 4; dd++) {
                float ac = (dd == 0) ? ax.x : (dd == 1) ? ax.y : (dd == 2) ? ax.z : ax.w;
                unsigned long long aa = dup2(ac);
                ulonglong2 wl = *(const ulonglong2*)&w1s[(dt + dd) * DH + j0];
                a0 = fma2(aa, wl.x, a0);
                a1 = fma2(aa, wl.y, a1);
            }
        }
        float f = 2.f * lrs[c] * (1.f / DH);
        float2 p01 = unpk2(a0), p23 = unpk2(a1);
        float4 vv = *(const float4*)&vs[c * DH + j0];
        float4 Gn = make_float4(f * (vv.x - p01.x), f * (vv.y - p01.y),
                                f * (vv.z - p23.x), f * (vv.w - p23.y));
        *(float4*)&vs[c * DH + j0] = Gn;
    }
    __syncthreads();

    // ---- GEMM C: dAn = Gn @ w1^T ; dhn = dAn * silu'(h)  (into hs) ----
    {
        unsigned long long a0 = 0ull, a1 = 0ull;
#pragma unroll 4
        for (int dt = 0; dt < DH; dt += 4) {
            float4 gx = *(const float4*)&vs[c * DH + dt];
#pragma unroll
            for (int dd = 0; dd < 4; dd++) {
                float gc = (dd == 0) ? gx.x : (dd == 1) ? gx.y : (dd == 2) ? gx.z : gx.w;
                unsigned long long gg = dup2(gc);
                ulonglong2 wl = *(const ulonglong2*)&w1ts[(dt + dd) * W1T_PAD + j0];
                a0 = fma2(gg, wl.x, a0);
                a1 = fma2(gg, wl.y, a1);
            }
        }
        float4 hv = *(const float4*)&hs[c * DH + j0];
        float2 d01 = unpk2(a0), d23 = unpk2(a1);
        float sg;
        sg = sigf(hv.x); d01.x *= sg * (1.f + hv.x * (1.f - sg));
        sg = sigf(hv.y); d01.y *= sg * (1.f + hv.y * (1.f - sg));
        sg = sigf(hv.z); d23.x *= sg * (1.f + hv.z * (1.f - sg));
        sg = sigf(hv.w); d23.y *= sg * (1.f + hv.w * (1.f - sg));
        *(float4*)&hs[c * DH + j0] = make_float4(d01.x, d01.y, d23.x, d23.y);
    }
    __syncthreads();

    // ---- Outer products: s1 = a^T @ Gn ; s0 = k^T @ dhn ----
    int d1g = tid >> 5;        // 0..15 -> 8 rows
    int d2g = tid & 31;        // 0..31 -> 4 cols
    int d1b = d1g * 8;
    int d2b = d2g * 4;

    // G1
    {
        unsigned long long acc[4][4];
#pragma unroll
        for (int rp = 0; rp < 4; rp++)
#pragma unroll
            for (int cc = 0; cc < 4; cc++) acc[rp][cc] = 0ull;
#pragma unroll
        for (int cc2 = 0; cc2 < CHUNK; cc2++) {
            ulonglong2 a01 = *(const ulonglong2*)&as_[cc2 * DH + d1b];
            ulonglong2 a23 = *(const ulonglong2*)&as_[cc2 * DH + d1b + 4];
            float4 gv = *(const float4*)&vs[cc2 * DH + d2b];
            unsigned long long g0 = dup2(gv.x), g1 = dup2(gv.y),
                               g2 = dup2(gv.z), g3 = dup2(gv.w);
            acc[0][0] = fma2(a01.x, g0, acc[0][0]);
            acc[0][1] = fma2(a01.x, g1, acc[0][1]);
            acc[0][2] = fma2(a01.x, g2, acc[0][2]);
            acc[0][3] = fma2(a01.x, g3, acc[0][3]);
            acc[1][0] = fma2(a01.y, g0, acc[1][0]);
            acc[1][1] = fma2(a01.y, g1, acc[1][1]);
            acc[1][2] = fma2(a01.y, g2, acc[1][2]);
            acc[1][3] = fma2(a01.y, g3, acc[1][3]);
            acc[2][0] = fma2(a23.x, g0, acc[2][0]);
            acc[2][1] = fma2(a23.x, g1, acc[2][1]);
            acc[2][2] = fma2(a23.x, g2, acc[2][2]);
            acc[2][3] = fma2(a23.x, g3, acc[2][3]);
            acc[3][0] = fma2(a23.y, g0, acc[3][0]);
            acc[3][1] = fma2(a23.y, g1, acc[3][1]);
            acc[3][2] = fma2(a23.y, g2, acc[3][2]);
            acc[3][3] = fma2(a23.y, g3, acc[3][3]);
        }
        float* o1 = out + ((size_t)((BH + bh) * NCHUNK + t)) * DH2;
#pragma unroll
        for (int rp = 0; rp < 4; rp++) {
            float2 u0 = unpk2(acc[rp][0]), u1 = unpk2(acc[rp][1]);
            float2 u2 = unpk2(acc[rp][2]), u3 = unpk2(acc[rp][3]);
            int rl = d1b + 2 * rp;
            *(float4*)(o1 + (size_t)rl * DH + d2b)       = make_float4(u0.x, u1.x, u2.x, u3.x);
            *(float4*)(o1 + (size_t)(rl + 1) * DH + d2b) = make_float4(u0.y, u1.y, u2.y, u3.y);
        }
    }

    // G0
    {
        unsigned long long acc[4][4];
#pragma unroll
        for (int rp = 0; rp < 4; rp++)
#pragma unroll
            for (int cc = 0; cc < 4; cc++) acc[rp][cc] = 0ull;
#pragma unroll
        for (int cc2 = 0; cc2 < CHUNK; cc2++) {
            ulonglong2 a01 = *(const ulonglong2*)&ks[cc2 * DH + d1b];
            ulonglong2 a23 = *(const ulonglong2*)&ks[cc2 * DH + d1b + 4];
            float4 gv = *(const float4*)&hs[cc2 * DH + d2b];
            unsigned long long g0 = dup2(gv.x), g1 = dup2(gv.y),
                               g2 = dup2(gv.z), g3 = dup2(gv.w);
            acc[0][0] = fma2(a01.x, g0, acc[0][0]);
            acc[0][1] = fma2(a01.x, g1, acc[0][1]);
            acc[0][2] = fma2(a01.x, g2, acc[0][2]);
            acc[0][3] = fma2(a01.x, g3, acc[0][3]);
            acc[1][0] = fma2(a01.y, g0, acc[1][0]);
            acc[1][1] = fma2(a01.y, g1, acc[1][1]);
            acc[1][2] = fma2(a01.y, g2, acc[1][2]);
            acc[1][3] = fma2(a01.y, g3, acc[1][3]);
            acc[2][0] = fma2(a23.x, g0, acc[2][0]);
            acc[2][1] = fma2(a23.x, g1, acc[2][1]);
            acc[2][2] = fma2(a23.x, g2, acc[2][2]);
            acc[2][3] = fma2(a23.x, g3, acc[2][3]);
            acc[3][0] = fma2(a23.y, g0, acc[3][0]);
            acc[3][1] = fma2(a23.y, g1, acc[3][1]);
            acc[3][2] = fma2(a23.y, g2, acc[3][2]);
            acc[3][3] = fma2(a23.y, g3, acc[3][3]);
        }
        float* o0 = out + ((size_t)(bh * NCHUNK + t)) * DH2;
#pragma unroll
        for (int rp = 0; rp < 4; rp++) {
            float2 u0 = unpk2(acc[rp][0]), u1 = unpk2(acc[rp][1]);
            float2 u2 = unpk2(acc[rp][2]), u3 = unpk2(acc[rp][3]);
            int rl = d1b + 2 * rp;
            *(float4*)(o0 + (size_t)rl * DH + d2b)       = make_float4(u0.x, u1.x, u2.x, u3.x);
            *(float4*)(o0 + (size_t)(rl + 1) * DH + d2b) = make_float4(u0.y, u1.y, u2.y, u3.y);
        }
    }
}

// ---------------- K5: fused momentum + decay scan (in place, float4) ----------------
// grid 512: sbh = blk>>5 (0..15), eb = blk&31; block 128 threads, each 1 float4
__global__ void k_scan(float* __restrict__ out) {
    __shared__ float moms[NCHUNK], decs[NCHUNK];
    int blk = blockIdx.x;
    int sbh = blk >> 5;
    int eb  = blk & 31;
    int bh  = sbh & 7;
    int tid = threadIdx.x;
    if (tid < NCHUNK) {
        moms[tid] = g_mom[bh * NCHUNK + tid];
        decs[tid] = 1.f - g_dec[bh * NCHUNK + tid];
    }
    __syncthreads();
    size_t base = (size_t)sbh * NCHUNK * DH2 + (size_t)eb * 512 + tid * 4;
    float4 m = make_float4(0.f, 0.f, 0.f, 0.f);
    float4 u = make_float4(0.f, 0.f, 0.f, 0.f);
#pragma unroll 4
    for (int t = 0; t < NCHUNK; t++) {
        size_t idx = base + (size_t)t * DH2;
        float4 sv = *(float4*)(out + idx);
        float mo = moms[t], de = decs[t];
        m.x = mo * m.x + sv.x;  m.y = mo * m.y + sv.y;
        m.z = mo * m.z + sv.z;  m.w = mo * m.w + sv.w;
        u.x = de * u.x + m.x;   u.y = de * u.y + m.y;
        u.z = de * u.z + m.z;   u.w = de * u.w + m.w;
        *(float4*)(out + idx) = u;
    }
}

// ---------------- launch ----------------
extern "C" void kernel_launch(void* const* d_in, const int* in_sizes, int n_in,
                              void* d_out, int out_size) {
    const float* seq   = (const float*)d_in[0];
    const float* scale = (const float*)d_in[1];
    const float* Wkv   = (const float*)d_in[2];
    const float* Wstep = (const float*)d_in[3];
    const float* Wmom  = (const float*)d_in[4];
    const float* Wdec  = (const float*)d_in[5];
    const float* w0    = (const float*)d_in[6];
    const float* w1    = (const float*)d_in[7];
    float* out = (float*)d_out;

    const int GRAD_SMEM = (16384 + 16384 + 128 * W1T_PAD + 4 * 2048 + 16) * 4;
    const int KV_SMEM = KV_ROWS * DIMD * 4;
    cudaFuncSetAttribute(k_grad, cudaFuncAttributeMaxDynamicSharedMemorySize, GRAD_SMEM);
    cudaFuncSetAttribute(k_kvproj, cudaFuncAttributeMaxDynamicSharedMemorySize, KV_SMEM);

    k_rmsnorm<<<BB * SS, 128>>>(seq, scale, Wstep);
    k_chunkstats<<<BB * NCHUNK, 128>>>(Wmom, Wdec);
    k_kvproj<<<512, 256, KV_SMEM>>>(Wkv);
    k_grad<<<BH * NCHUNK, 512, GRAD_SMEM>>>(w0, w1, out);
    k_scan<<<512, 128>>>(out);
}

// round 3
// speedup vs baseline: 1.6853x; 1.2924x over previous
#include <cuda_runtime.h>
#include <math.h>

#define BB 2
#define SS 2048
#define DIMD 512
#define HEADS 4
#define DH 128
#define CHUNK 16
#define NCHUNK 128
#define BH 8
#define DH2 16384
#define MAX_LR 0.01f
#define EPSV 1e-6f

// ---------------- scratch ----------------
__device__ float g_xnorm[BB*SS*DIMD];
__device__ float g_k[BH*NCHUNK*CHUNK*DH];
__device__ float g_v[BH*NCHUNK*CHUNK*DH];
__device__ float g_lr[BH*NCHUNK*CHUNK];
__device__ float g_mom[BH*NCHUNK];
__device__ float g_dec[BH*NCHUNK];

__device__ __forceinline__ float sigf(float x) { return 1.f / (1.f + __expf(-x)); }

// ------- packed f32x2 helpers -------
__device__ __forceinline__ unsigned long long fma2(unsigned long long a,
                                                   unsigned long long b,
                                                   unsigned long long c) {
    unsigned long long d;
    asm("fma.rn.f32x2 %0, %1, %2, %3;" : "=l"(d) : "l"(a), "l"(b), "l"(c));
    return d;
}
__device__ __forceinline__ unsigned long long dup2(float x) {
    unsigned long long d;
    unsigned int xi = __float_as_uint(x);
    asm("mov.b64 %0, {%1, %1};" : "=l"(d) : "r"(xi));
    return d;
}
__device__ __forceinline__ float2 unpk2(unsigned long long v) {
    unsigned int lo, hi;
    asm("mov.b64 {%0, %1}, %2;" : "=r"(lo), "=r"(hi) : "l"(v));
    return make_float2(__uint_as_float(lo), __uint_as_float(hi));
}

// ---------------- K1: RMSNorm + per-token lr ----------------
__global__ void k_rmsnorm(const float* __restrict__ seq,
                          const float* __restrict__ scale,
                          const float* __restrict__ Wstep) {
    int tok = blockIdx.x;
    int tid = threadIdx.x;
    int lane = tid & 31, warp = tid >> 5;
    __shared__ float red[4];
    __shared__ float redp[4][4];

    float4 v = ((const float4*)(seq + (size_t)tok * DIMD))[tid];
    float ss = v.x*v.x + v.y*v.y + v.z*v.z + v.w*v.w;
#pragma unroll
    for (int o = 16; o; o >>= 1) ss += __shfl_xor_sync(0xffffffffu, ss, o);
    if (lane == 0) red[warp] = ss;
    __syncthreads();
    float tot = red[0] + red[1] + red[2] + red[3];
    float inv = rsqrtf(tot * (1.f / DIMD) + EPSV);

    float4 sc = ((const float4*)scale)[tid];
    float4 xn = make_float4(v.x*inv*sc.x, v.y*inv*sc.y, v.z*inv*sc.z, v.w*inv*sc.w);
    ((float4*)(g_xnorm + (size_t)tok * DIMD))[tid] = xn;

    int d0 = tid * 4;
    float4 wa = ((const float4*)Wstep)[d0 + 0];
    float4 wb = ((const float4*)Wstep)[d0 + 1];
    float4 wc = ((const float4*)Wstep)[d0 + 2];
    float4 wd = ((const float4*)Wstep)[d0 + 3];
    float p0 = xn.x*wa.x + xn.y*wb.x + xn.z*wc.x + xn.w*wd.x;
    float p1 = xn.x*wa.y + xn.y*wb.y + xn.z*wc.y + xn.w*wd.y;
    float p2 = xn.x*wa.z + xn.y*wb.z + xn.z*wc.z + xn.w*wd.z;
    float p3 = xn.x*wa.w + xn.y*wb.w + xn.z*wc.w + xn.w*wd.w;
#pragma unroll
    for (int o = 16; o; o >>= 1) {
        p0 += __shfl_xor_sync(0xffffffffu, p0, o);
        p1 += __shfl_xor_sync(0xffffffffu, p1, o);
        p2 += __shfl_xor_sync(0xffffffffu, p2, o);
        p3 += __shfl_xor_sync(0xffffffffu, p3, o);
    }
    if (lane == 0) { redp[warp][0] = p0; redp[warp][1] = p1; redp[warp][2] = p2; redp[warp][3] = p3; }
    __syncthreads();
    if (tid < 4) {
        float p = redp[0][tid] + redp[1][tid] + redp[2][tid] + redp[3][tid];
        float lrv = MAX_LR * sigf(p);
        int b = tok / SS, s = tok % SS;
        int t = s / CHUNK, c = s % CHUNK;
        g_lr[(((b * HEADS + tid) * NCHUNK + t) * CHUNK) + c] = lrv;
    }
}

// ---------------- K2: chunk means -> mom/dec ----------------
__global__ void k_chunkstats(const float* __restrict__ Wmom,
                             const float* __restrict__ Wdec) {
    int blk = blockIdx.x;
    int b = blk / NCHUNK, t = blk % NCHUNK;
    int tid = threadIdx.x;
    int lane = tid & 31, warp = tid >> 5;
    __shared__ float redp[4][8];

    int d0 = tid * 4;
    const float* xb = g_xnorm + ((size_t)(b * SS + t * CHUNK)) * DIMD;
    float4 m = make_float4(0.f, 0.f, 0.f, 0.f);
#pragma unroll
    for (int c = 0; c < CHUNK; c++) {
        float4 v = *(const float4*)(xb + (size_t)c * DIMD + d0);
        m.x += v.x; m.y += v.y; m.z += v.z; m.w += v.w;
    }
    m.x *= (1.f/CHUNK); m.y *= (1.f/CHUNK); m.z *= (1.f/CHUNK); m.w *= (1.f/CHUNK);

    float4 ma = ((const float4*)Wmom)[d0 + 0];
    float4 mb = ((const float4*)Wmom)[d0 + 1];
    float4 mc = ((const float4*)Wmom)[d0 + 2];
    float4 md = ((const float4*)Wmom)[d0 + 3];
    float4 da = ((const float4*)Wdec)[d0 + 0];
    float4 db = ((const float4*)Wdec)[d0 + 1];
    float4 dc = ((const float4*)Wdec)[d0 + 2];
    float4 dd = ((const float4*)Wdec)[d0 + 3];

    float p[8];
    p[0] = m.x*ma.x + m.y*mb.x + m.z*mc.x + m.w*md.x;
    p[1] = m.x*ma.y + m.y*mb.y + m.z*mc.y + m.w*md.y;
    p[2] = m.x*ma.z + m.y*mb.z + m.z*mc.z + m.w*md.z;
    p[3] = m.x*ma.w + m.y*mb.w + m.z*mc.w + m.w*md.w;
    p[4] = m.x*da.x + m.y*db.x + m.z*dc.x + m.w*dd.x;
    p[5] = m.x*da.y + m.y*db.y + m.z*dc.y + m.w*dd.y;
    p[6] = m.x*da.z + m.y*db.z + m.z*dc.z + m.w*dd.z;
    p[7] = m.x*da.w + m.y*db.w + m.z*dc.w + m.w*dd.w;
#pragma unroll
    for (int i = 0; i < 8; i++) {
#pragma unroll
        for (int o = 16; o; o >>= 1) p[i] += __shfl_xor_sync(0xffffffffu, p[i], o);
    }
    if (lane == 0) {
#pragma unroll
        for (int i = 0; i < 8; i++) redp[warp][i] = p[i];
    }
    __syncthreads();
    if (tid < 8) {
        float s = redp[0][tid] + redp[1][tid] + redp[2][tid] + redp[3][tid];
        float sv = sigf(s);
        int h = tid & 3;
        if (tid < 4) g_mom[(b * HEADS + h) * NCHUNK + t] = sv;
        else         g_dec[(b * HEADS + h) * NCHUNK + t] = sv;
    }
}

// ---------------- K3: kv projection (tiled, f32x2) ----------------
#define KV_ROWS 32
__global__ void __launch_bounds__(256, 2) k_kvproj(const float* __restrict__ Wkv) {
    extern __shared__ float xs[];
    int rg  = blockIdx.x & 127;
    int cgp = blockIdx.x >> 7;
    int tid = threadIdx.x;

    const float4* src = (const float4*)(g_xnorm + (size_t)rg * KV_ROWS * DIMD);
#pragma unroll
    for (int i = tid; i < KV_ROWS * DIMD / 4; i += 256) ((float4*)xs)[i] = src[i];
    __syncthreads();

    int rs = tid >> 6;
    int cg = tid & 63;
    int r0 = rs * 8;
    int col = cgp * 256 + cg * 4;

    unsigned long long acc[8][2];
#pragma unroll
    for (int r = 0; r < 8; r++) { acc[r][0] = 0ull; acc[r][1] = 0ull; }

    const float* wbase = Wkv + col;
#pragma unroll 2
    for (int dt = 0; dt < DIMD; dt += 4) {
        float4 xv[8];
#pragma unroll
        for (int r = 0; r < 8; r++) xv[r] = *(const float4*)&xs[(r0 + r) * DIMD + dt];
#pragma unroll
        for (int dd = 0; dd < 4; dd++) {
            ulonglong2 wl = *(const ulonglong2*)(wbase + (size_t)(dt + dd) * 1024);
#pragma unroll
            for (int r = 0; r < 8; r++) {
                float xc = (dd == 0) ? xv[r].x : (dd == 1) ? xv[r].y : (dd == 2) ? xv[r].z : xv[r].w;
                unsigned long long kk = dup2(xc);
                acc[r][0] = fma2(kk, wl.x, acc[r][0]);
                acc[r][1] = fma2(kk, wl.y, acc[r][1]);
            }
        }
    }

    int isv = (col >= 512);
    int c2 = col - isv * 512;
    int h = c2 >> 7, j = c2 & 127;
    float* base = (isv ? g_v : g_k);
#pragma unroll
    for (int r = 0; r < 8; r++) {
        int tg = rg * KV_ROWS + r0 + r;
        int b = tg >> 11, s = tg & 2047;
        float* dst = base + ((size_t)((b * HEADS + h) * SS + s)) * DH + j;
        *(ulonglong2*)dst = make_ulonglong2(acc[r][0], acc[r][1]);
    }
}

// ---------------- K4: per-chunk gradients (4 chunks/CTA, 4x4 reg tiles) ----------------
#define CPG 4
#define MROWS 64
#define WPITCH 140

// acc[c][j] += sum_d A[c0+c][d] * W[d][j0+j]   (A rows broadcast, W rows conflict-free)
__device__ __forceinline__ void gemm64(const float* __restrict__ A,
                                       const float* __restrict__ W,
                                       int c0, int j0,
                                       unsigned long long acc[4][2]) {
#pragma unroll
    for (int i = 0; i < 4; i++) { acc[i][0] = 0ull; acc[i][1] = 0ull; }
#pragma unroll 2
    for (int dq = 0; dq < DH; dq += 4) {
        float4 ar[4];
#pragma unroll
        for (int i = 0; i < 4; i++) ar[i] = *(const float4*)&A[(c0 + i) * DH + dq];
#pragma unroll
        for (int dd = 0; dd < 4; dd++) {
            ulonglong2 w = *(const ulonglong2*)&W[(dq + dd) * WPITCH + j0];
#pragma unroll
            for (int i = 0; i < 4; i++) {
                float av = (dd == 0) ? ar[i].x : (dd == 1) ? ar[i].y : (dd == 2) ? ar[i].z : ar[i].w;
                unsigned long long aa = dup2(av);
                acc[i][0] = fma2(aa, w.x, acc[i][0]);
                acc[i][1] = fma2(aa, w.y, acc[i][1]);
            }
        }
    }
}

// out[d1+r][d2+c] = sum_cc Arows[crow][d1+r] * Grows[crow][d2+c], 8x4 tile
__device__ __forceinline__ void outer16(const float* __restrict__ Arows,
                                        const float* __restrict__ Grows,
                                        int crowbase, int d1, int d2,
                                        float* __restrict__ o) {
    unsigned long long acc[4][4];
#pragma unroll
    for (int rp = 0; rp < 4; rp++)
#pragma unroll
        for (int cc = 0; cc < 4; cc++) acc[rp][cc] = 0ull;
#pragma unroll
    for (int cc2 = 0; cc2 < CHUNK; cc2++) {
        int crow = crowbase + cc2;
        ulonglong2 a01 = *(const ulonglong2*)&Arows[crow * DH + d1];
        ulonglong2 a23 = *(const ulonglong2*)&Arows[crow * DH + d1 + 4];
        float4 gv = *(const float4*)&Grows[crow * DH + d2];
        unsigned long long g0 = dup2(gv.x), g1 = dup2(gv.y),
                           g2 = dup2(gv.z), g3 = dup2(gv.w);
        acc[0][0] = fma2(a01.x, g0, acc[0][0]);
        acc[0][1] = fma2(a01.x, g1, acc[0][1]);
        acc[0][2] = fma2(a01.x, g2, acc[0][2]);
        acc[0][3] = fma2(a01.x, g3, acc[0][3]);
        acc[1][0] = fma2(a01.y, g0, acc[1][0]);
        acc[1][1] = fma2(a01.y, g1, acc[1][1]);
        acc[1][2] = fma2(a01.y, g2, acc[1][2]);
        acc[1][3] = fma2(a01.y, g3, acc[1][3]);
        acc[2][0] = fma2(a23.x, g0, acc[2][0]);
        acc[2][1] = fma2(a23.x, g1, acc[2][1]);
        acc[2][2] = fma2(a23.x, g2, acc[2][2]);
        acc[2][3] = fma2(a23.x, g3, acc[2][3]);
        acc[3][0] = fma2(a23.y, g0, acc[3][0]);
        acc[3][1] = fma2(a23.y, g1, acc[3][1]);
        acc[3][2] = fma2(a23.y, g2, acc[3][2]);
        acc[3][3] = fma2(a23.y, g3, acc[3][3]);
    }
#pragma unroll
    for (int rp = 0; rp < 4; rp++) {
        float2 u0 = unpk2(acc[rp][0]), u1 = unpk2(acc[rp][1]);
        float2 u2 = unpk2(acc[rp][2]), u3 = unpk2(acc[rp][3]);
        int rl = d1 + 2 * rp;
        *(float4*)(o + (size_t)rl * DH + d2)       = make_float4(u0.x, u1.x, u2.x, u3.x);
        *(float4*)(o + (size_t)(rl + 1) * DH + d2) = make_float4(u0.y, u1.y, u2.y, u3.y);
    }
}

__global__ void __launch_bounds__(512, 1)
k_grad(const float* __restrict__ w0g_all, const float* __restrict__ w1g_all,
       float* __restrict__ out) {
    extern __shared__ float sm[];
    float* ws  = sm;                        // 128*140 = 17920
    float* ks  = ws + 128 * WPITCH;         // 64*128 = 8192
    float* vs  = ks + MROWS * DH;           // v -> Gn
    float* as_ = vs + MROWS * DH;           // silu(h)
    float* ss  = as_ + MROWS * DH;          // sigma(h) -> dhn
    float* lrs = ss + MROWS * DH;           // 64

    int bh = blockIdx.x >> 5;
    int tg = blockIdx.x & 31;
    int t0 = tg * CPG;
    int tid = threadIdx.x;

    // ---- load k, v, lr, w0 ----
    const float4* kg = (const float4*)(g_k + ((size_t)(bh * NCHUNK + t0)) * (CHUNK * DH));
    const float4* vg = (const float4*)(g_v + ((size_t)(bh * NCHUNK + t0)) * (CHUNK * DH));
    for (int i = tid; i < MROWS * DH / 4; i += 512) {
        ((float4*)ks)[i] = kg[i];
        ((float4*)vs)[i] = vg[i];
    }
    if (tid < MROWS) lrs[tid] = g_lr[(bh * NCHUNK + t0) * CHUNK + tid];
    const float4* w0g4 = (const float4*)(w0g_all + (size_t)bh * DH2);
    for (int i = tid; i < 4096; i += 512) {
        int row = i >> 5, col = (i & 31) * 4;
        *(float4*)&ws[row * WPITCH + col] = w0g4[i];
    }
    __syncthreads();

    int ty = tid >> 5, tx = tid & 31;
    int c0 = ty * 4, j0 = tx * 4;
    unsigned long long acc[4][2];

    // ---- GEMM A: h = k @ w0 ; store sigma(h), silu(h) ----
    gemm64(ks, ws, c0, j0, acc);
#pragma unroll
    for (int i = 0; i < 4; i++) {
        float2 h01 = unpk2(acc[i][0]), h23 = unpk2(acc[i][1]);
        float s0 = sigf(h01.x), s1 = sigf(h01.y), s2 = sigf(h23.x), s3 = sigf(h23.y);
        *(float4*)&ss[(c0 + i) * DH + j0]  = make_float4(s0, s1, s2, s3);
        *(float4*)&as_[(c0 + i) * DH + j0] = make_float4(h01.x * s0, h01.y * s1, h23.x * s2, h23.y * s3);
    }
    __syncthreads();

    // ---- load w1 ----
    const float4* w1g4 = (const float4*)(w1g_all + (size_t)bh * DH2);
    for (int i = tid; i < 4096; i += 512) {
        int row = i >> 5, col = (i & 31) * 4;
        *(float4*)&ws[row * WPITCH + col] = w1g4[i];
    }
    __syncthreads();

    // ---- GEMM B: pred = a @ w1 ; Gn = f*(v - pred) into vs ----
    gemm64(as_, ws, c0, j0, acc);
#pragma unroll
    for (int i = 0; i < 4; i++) {
        float f = 2.f * lrs[c0 + i] * (1.f / DH);
        float2 p01 = unpk2(acc[i][0]), p23 = unpk2(acc[i][1]);
        float4 vv = *(const float4*)&vs[(c0 + i) * DH + j0];
        *(float4*)&vs[(c0 + i) * DH + j0] =
            make_float4(f * (vv.x - p01.x), f * (vv.y - p01.y),
                        f * (vv.z - p23.x), f * (vv.w - p23.y));
    }
    __syncthreads();

    // ---- load w1^T (coalesced read, scattered smem store) ----
    {
        const float* w1g = w1g_all + (size_t)bh * DH2;
        for (int i = tid; i < DH2; i += 512) {
            ws[(i & 127) * WPITCH + (i >> 7)] = w1g[i];
        }
    }
    __syncthreads();

    int d1 = (tid >> 5) * 8, d2 = (tid & 31) * 4;

    // ---- G1: s1 = a^T @ Gn per chunk (doesn't touch ws/ss) ----
#pragma unroll
    for (int ch = 0; ch < CPG; ch++) {
        float* o1 = out + ((size_t)((BH + bh) * NCHUNK + t0 + ch)) * DH2;
        outer16(as_, vs, ch * CHUNK, d1, d2, o1);
    }

    // ---- GEMM C: dA = Gn @ w1^T ; dhn = dA * (s + a*(1-s)) into ss ----
    gemm64(vs, ws, c0, j0, acc);
#pragma unroll
    for (int i = 0; i < 4; i++) {
        float2 d01 = unpk2(acc[i][0]), d23 = unpk2(acc[i][1]);
        float4 sv = *(const float4*)&ss[(c0 + i) * DH + j0];
        float4 av = *(const float4*)&as_[(c0 + i) * DH + j0];
        d01.x *= sv.x + av.x * (1.f - sv.x);
        d01.y *= sv.y + av.y * (1.f - sv.y);
        d23.x *= sv.z + av.z * (1.f - sv.z);
        d23.y *= sv.w + av.w * (1.f - sv.w);
        *(float4*)&ss[(c0 + i) * DH + j0] = make_float4(d01.x, d01.y, d23.x, d23.y);
    }
    __syncthreads();

    // ---- G0: s0 = k^T @ dhn per chunk ----
#pragma unroll
    for (int ch = 0; ch < CPG; ch++) {
        float* o0 = out + ((size_t)(bh * NCHUNK + t0 + ch)) * DH2;
        outer16(ks, ss, ch * CHUNK, d1, d2, o0);
    }
}

// ---------------- K5: fused momentum + decay scan ----------------
__global__ void k_scan(float* __restrict__ out) {
    __shared__ float moms[NCHUNK], decs[NCHUNK];
    int blk = blockIdx.x;
    int sbh = blk >> 5;
    int eb  = blk & 31;
    int bh  = sbh & 7;
    int tid = threadIdx.x;
    if (tid < NCHUNK) {
        moms[tid] = g_mom[bh * NCHUNK + tid];
        decs[tid] = 1.f - g_dec[bh * NCHUNK + tid];
    }
    __syncthreads();
    size_t base = (size_t)sbh * NCHUNK * DH2 + (size_t)eb * 512 + tid * 4;
    float4 m = make_float4(0.f, 0.f, 0.f, 0.f);
    float4 u = make_float4(0.f, 0.f, 0.f, 0.f);
#pragma unroll 4
    for (int t = 0; t < NCHUNK; t++) {
        size_t idx = base + (size_t)t * DH2;
        float4 sv = *(float4*)(out + idx);
        float mo = moms[t], de = decs[t];
        m.x = mo * m.x + sv.x;  m.y = mo * m.y + sv.y;
        m.z = mo * m.z + sv.z;  m.w = mo * m.w + sv.w;
        u.x = de * u.x + m.x;   u.y = de * u.y + m.y;
        u.z = de * u.z + m.z;   u.w = de * u.w + m.w;
        *(float4*)(out + idx) = u;
    }
}

// ---------------- launch ----------------
extern "C" void kernel_launch(void* const* d_in, const int* in_sizes, int n_in,
                              void* d_out, int out_size) {
    const float* seq   = (const float*)d_in[0];
    const float* scale = (const float*)d_in[1];
    const float* Wkv   = (const float*)d_in[2];
    const float* Wstep = (const float*)d_in[3];
    const float* Wmom  = (const float*)d_in[4];
    const float* Wdec  = (const float*)d_in[5];
    const float* w0    = (const float*)d_in[6];
    const float* w1    = (const float*)d_in[7];
    float* out = (float*)d_out;

    const int GRAD_SMEM = (128 * WPITCH + 4 * MROWS * DH + 64) * 4;  // 203008 B
    const int KV_SMEM = KV_ROWS * DIMD * 4;
    cudaFuncSetAttribute(k_grad, cudaFuncAttributeMaxDynamicSharedMemorySize, GRAD_SMEM);
    cudaFuncSetAttribute(k_kvproj, cudaFuncAttributeMaxDynamicSharedMemorySize, KV_SMEM);

    k_rmsnorm<<<BB * SS, 128>>>(seq, scale, Wstep);
    k_chunkstats<<<BB * NCHUNK, 128>>>(Wmom, Wdec);
    k_kvproj<<<512, 256, KV_SMEM>>>(Wkv);
    k_grad<<<BH * (NCHUNK / CPG), 512, GRAD_SMEM>>>(w0, w1, out);
    k_scan<<<512, 128>>>(out);
}

// round 4
// speedup vs baseline: 1.6870x; 1.0010x over previous
#include <cuda_runtime.h>
#include <math.h>

#define BB 2
#define SS 2048
#define DIMD 512
#define HEADS 4
#define DH 128
#define CHUNK 16
#define NCHUNK 128
#define BH 8
#define DH2 16384
#define MAX_LR 0.01f
#define EPSV 1e-6f

// ---------------- scratch ----------------
__device__ float g_xnorm[BB*SS*DIMD];
__device__ float g_k[BH*NCHUNK*CHUNK*DH];
__device__ float g_v[BH*NCHUNK*CHUNK*DH];
__device__ float g_lr[BH*NCHUNK*CHUNK];
__device__ float g_mom[BH*NCHUNK];
__device__ float g_dec[BH*NCHUNK];

__device__ __forceinline__ float sigf(float x) { return 1.f / (1.f + __expf(-x)); }

// ------- packed f32x2 helpers -------
__device__ __forceinline__ unsigned long long fma2(unsigned long long a,
                                                   unsigned long long b,
                                                   unsigned long long c) {
    unsigned long long d;
    asm("fma.rn.f32x2 %0, %1, %2, %3;" : "=l"(d) : "l"(a), "l"(b), "l"(c));
    return d;
}
__device__ __forceinline__ unsigned long long dup2(float x) {
    unsigned long long d;
    unsigned int xi = __float_as_uint(x);
    asm("mov.b64 %0, {%1, %1};" : "=l"(d) : "r"(xi));
    return d;
}
__device__ __forceinline__ float2 unpk2(unsigned long long v) {
    unsigned int lo, hi;
    asm("mov.b64 {%0, %1}, %2;" : "=r"(lo), "=r"(hi) : "l"(v));
    return make_float2(__uint_as_float(lo), __uint_as_float(hi));
}

// ---------------- K1: RMSNorm + per-token lr ----------------
__global__ void k_rmsnorm(const float* __restrict__ seq,
                          const float* __restrict__ scale,
                          const float* __restrict__ Wstep) {
    int tok = blockIdx.x;
    int tid = threadIdx.x;
    int lane = tid & 31, warp = tid >> 5;
    __shared__ float red[4];
    __shared__ float redp[4][4];

    float4 v = ((const float4*)(seq + (size_t)tok * DIMD))[tid];
    float ss = v.x*v.x + v.y*v.y + v.z*v.z + v.w*v.w;
#pragma unroll
    for (int o = 16; o; o >>= 1) ss += __shfl_xor_sync(0xffffffffu, ss, o);
    if (lane == 0) red[warp] = ss;
    __syncthreads();
    float tot = red[0] + red[1] + red[2] + red[3];
    float inv = rsqrtf(tot * (1.f / DIMD) + EPSV);

    float4 sc = ((const float4*)scale)[tid];
    float4 xn = make_float4(v.x*inv*sc.x, v.y*inv*sc.y, v.z*inv*sc.z, v.w*inv*sc.w);
    ((float4*)(g_xnorm + (size_t)tok * DIMD))[tid] = xn;

    int d0 = tid * 4;
    float4 wa = ((const float4*)Wstep)[d0 + 0];
    float4 wb = ((const float4*)Wstep)[d0 + 1];
    float4 wc = ((const float4*)Wstep)[d0 + 2];
    float4 wd = ((const float4*)Wstep)[d0 + 3];
    float p0 = xn.x*wa.x + xn.y*wb.x + xn.z*wc.x + xn.w*wd.x;
    float p1 = xn.x*wa.y + xn.y*wb.y + xn.z*wc.y + xn.w*wd.y;
    float p2 = xn.x*wa.z + xn.y*wb.z + xn.z*wc.z + xn.w*wd.z;
    float p3 = xn.x*wa.w + xn.y*wb.w + xn.z*wc.w + xn.w*wd.w;
#pragma unroll
    for (int o = 16; o; o >>= 1) {
        p0 += __shfl_xor_sync(0xffffffffu, p0, o);
        p1 += __shfl_xor_sync(0xffffffffu, p1, o);
        p2 += __shfl_xor_sync(0xffffffffu, p2, o);
        p3 += __shfl_xor_sync(0xffffffffu, p3, o);
    }
    if (lane == 0) { redp[warp][0] = p0; redp[warp][1] = p1; redp[warp][2] = p2; redp[warp][3] = p3; }
    __syncthreads();
    if (tid < 4) {
        float p = redp[0][tid] + redp[1][tid] + redp[2][tid] + redp[3][tid];
        float lrv = MAX_LR * sigf(p);
        int b = tok / SS, s = tok % SS;
        int t = s / CHUNK, c = s % CHUNK;
        g_lr[(((b * HEADS + tid) * NCHUNK + t) * CHUNK) + c] = lrv;
    }
}

// ---------------- K2: chunk means -> mom/dec ----------------
__global__ void k_chunkstats(const float* __restrict__ Wmom,
                             const float* __restrict__ Wdec) {
    int blk = blockIdx.x;
    int b = blk / NCHUNK, t = blk % NCHUNK;
    int tid = threadIdx.x;
    int lane = tid & 31, warp = tid >> 5;
    __shared__ float redp[4][8];

    int d0 = tid * 4;
    const float* xb = g_xnorm + ((size_t)(b * SS + t * CHUNK)) * DIMD;
    float4 m = make_float4(0.f, 0.f, 0.f, 0.f);
#pragma unroll
    for (int c = 0; c < CHUNK; c++) {
        float4 v = *(const float4*)(xb + (size_t)c * DIMD + d0);
        m.x += v.x; m.y += v.y; m.z += v.z; m.w += v.w;
    }
    m.x *= (1.f/CHUNK); m.y *= (1.f/CHUNK); m.z *= (1.f/CHUNK); m.w *= (1.f/CHUNK);

    float4 ma = ((const float4*)Wmom)[d0 + 0];
    float4 mb = ((const float4*)Wmom)[d0 + 1];
    float4 mc = ((const float4*)Wmom)[d0 + 2];
    float4 md = ((const float4*)Wmom)[d0 + 3];
    float4 da = ((const float4*)Wdec)[d0 + 0];
    float4 db = ((const float4*)Wdec)[d0 + 1];
    float4 dc = ((const float4*)Wdec)[d0 + 2];
    float4 dd = ((const float4*)Wdec)[d0 + 3];

    float p[8];
    p[0] = m.x*ma.x + m.y*mb.x + m.z*mc.x + m.w*md.x;
    p[1] = m.x*ma.y + m.y*mb.y + m.z*mc.y + m.w*md.y;
    p[2] = m.x*ma.z + m.y*mb.z + m.z*mc.z + m.w*md.z;
    p[3] = m.x*ma.w + m.y*mb.w + m.z*mc.w + m.w*md.w;
    p[4] = m.x*da.x + m.y*db.x + m.z*dc.x + m.w*dd.x;
    p[5] = m.x*da.y + m.y*db.y + m.z*dc.y + m.w*dd.y;
    p[6] = m.x*da.z + m.y*db.z + m.z*dc.z + m.w*dd.z;
    p[7] = m.x*da.w + m.y*db.w + m.z*dc.w + m.w*dd.w;
#pragma unroll
    for (int i = 0; i < 8; i++) {
#pragma unroll
        for (int o = 16; o; o >>= 1) p[i] += __shfl_xor_sync(0xffffffffu, p[i], o);
    }
    if (lane == 0) {
#pragma unroll
        for (int i = 0; i < 8; i++) redp[warp][i] = p[i];
    }
    __syncthreads();
    if (tid < 8) {
        float s = redp[0][tid] + redp[1][tid] + redp[2][tid] + redp[3][tid];
        float sv = sigf(s);
        int h = tid & 3;
        if (tid < 4) g_mom[(b * HEADS + h) * NCHUNK + t] = sv;
        else         g_dec[(b * HEADS + h) * NCHUNK + t] = sv;
    }
}

// ---------------- K3: kv projection (tiled, f32x2) ----------------
#define KV_ROWS 32
__global__ void __launch_bounds__(256, 2) k_kvproj(const float* __restrict__ Wkv) {
    extern __shared__ float xs[];
    int rg  = blockIdx.x & 127;
    int cgp = blockIdx.x >> 7;
    int tid = threadIdx.x;

    const float4* src = (const float4*)(g_xnorm + (size_t)rg * KV_ROWS * DIMD);
#pragma unroll
    for (int i = tid; i < KV_ROWS * DIMD / 4; i += 256) ((float4*)xs)[i] = src[i];
    __syncthreads();

    int rs = tid >> 6;
    int cg = tid & 63;
    int r0 = rs * 8;
    int col = cgp * 256 + cg * 4;

    unsigned long long acc[8][2];
#pragma unroll
    for (int r = 0; r < 8; r++) { acc[r][0] = 0ull; acc[r][1] = 0ull; }

    const float* wbase = Wkv + col;
#pragma unroll 2
    for (int dt = 0; dt < DIMD; dt += 4) {
        float4 xv[8];
#pragma unroll
        for (int r = 0; r < 8; r++) xv[r] = *(const float4*)&xs[(r0 + r) * DIMD + dt];
#pragma unroll
        for (int dd = 0; dd < 4; dd++) {
            ulonglong2 wl = *(const ulonglong2*)(wbase + (size_t)(dt + dd) * 1024);
#pragma unroll
            for (int r = 0; r < 8; r++) {
                float xc = (dd == 0) ? xv[r].x : (dd == 1) ? xv[r].y : (dd == 2) ? xv[r].z : xv[r].w;
                unsigned long long kk = dup2(xc);
                acc[r][0] = fma2(kk, wl.x, acc[r][0]);
                acc[r][1] = fma2(kk, wl.y, acc[r][1]);
            }
        }
    }

    int isv = (col >= 512);
    int c2 = col - isv * 512;
    int h = c2 >> 7, j = c2 & 127;
    float* base = (isv ? g_v : g_k);
#pragma unroll
    for (int r = 0; r < 8; r++) {
        int tg = rg * KV_ROWS + r0 + r;
        int b = tg >> 11, s = tg & 2047;
        float* dst = base + ((size_t)((b * HEADS + h) * SS + s)) * DH + j;
        *(ulonglong2*)dst = make_ulonglong2(acc[r][0], acc[r][1]);
    }
}

// ---------------- K4: per-chunk gradients (4 chunks/CTA, 4x4 reg tiles) ----------------
#define CPG 4
#define MROWS 64
#define WPITCH 140

// acc[c][j] += sum_d A[c0+c][d] * W[d][j0+j]   (A rows broadcast, W rows conflict-free)
__device__ __forceinline__ void gemm64(const float* __restrict__ A,
                                       const float* __restrict__ W,
                                       int c0, int j0,
                                       unsigned long long acc[4][2]) {
#pragma unroll
    for (int i = 0; i < 4; i++) { acc[i][0] = 0ull; acc[i][1] = 0ull; }
#pragma unroll 2
    for (int dq = 0; dq < DH; dq += 4) {
        float4 ar[4];
#pragma unroll
        for (int i = 0; i < 4; i++) ar[i] = *(const float4*)&A[(c0 + i) * DH + dq];
#pragma unroll
        for (int dd = 0; dd < 4; dd++) {
            ulonglong2 w = *(const ulonglong2*)&W[(dq + dd) * WPITCH + j0];
#pragma unroll
            for (int i = 0; i < 4; i++) {
                float av = (dd == 0) ? ar[i].x : (dd == 1) ? ar[i].y : (dd == 2) ? ar[i].z : ar[i].w;
                unsigned long long aa = dup2(av);
                acc[i][0] = fma2(aa, w.x, acc[i][0]);
                acc[i][1] = fma2(aa, w.y, acc[i][1]);
            }
        }
    }
}

// out[d1+r][d2+c] = sum_cc Arows[crow][d1+r] * Grows[crow][d2+c], 8x4 tile
__device__ __forceinline__ void outer16(const float* __restrict__ Arows,
                                        const float* __restrict__ Grows,
                                        int crowbase, int d1, int d2,
                                        float* __restrict__ o) {
    unsigned long long acc[4][4];
#pragma unroll
    for (int rp = 0; rp < 4; rp++)
#pragma unroll
        for (int cc = 0; cc < 4; cc++) acc[rp][cc] = 0ull;
#pragma unroll
    for (int cc2 = 0; cc2 < CHUNK; cc2++) {
        int crow = crowbase + cc2;
        ulonglong2 a01 = *(const ulonglong2*)&Arows[crow * DH + d1];
        ulonglong2 a23 = *(const ulonglong2*)&Arows[crow * DH + d1 + 4];
        float4 gv = *(const float4*)&Grows[crow * DH + d2];
        unsigned long long g0 = dup2(gv.x), g1 = dup2(gv.y),
                           g2 = dup2(gv.z), g3 = dup2(gv.w);
        acc[0][0] = fma2(a01.x, g0, acc[0][0]);
        acc[0][1] = fma2(a01.x, g1, acc[0][1]);
        acc[0][2] = fma2(a01.x, g2, acc[0][2]);
        acc[0][3] = fma2(a01.x, g3, acc[0][3]);
        acc[1][0] = fma2(a01.y, g0, acc[1][0]);
        acc[1][1] = fma2(a01.y, g1, acc[1][1]);
        acc[1][2] = fma2(a01.y, g2, acc[1][2]);
        acc[1][3] = fma2(a01.y, g3, acc[1][3]);
        acc[2][0] = fma2(a23.x, g0, acc[2][0]);
        acc[2][1] = fma2(a23.x, g1, acc[2][1]);
        acc[2][2] = fma2(a23.x, g2, acc[2][2]);
        acc[2][3] = fma2(a23.x, g3, acc[2][3]);
        acc[3][0] = fma2(a23.y, g0, acc[3][0]);
        acc[3][1] = fma2(a23.y, g1, acc[3][1]);
        acc[3][2] = fma2(a23.y, g2, acc[3][2]);
        acc[3][3] = fma2(a23.y, g3, acc[3][3]);
    }
#pragma unroll
    for (int rp = 0; rp < 4; rp++) {
        float2 u0 = unpk2(acc[rp][0]), u1 = unpk2(acc[rp][1]);
        float2 u2 = unpk2(acc[rp][2]), u3 = unpk2(acc[rp][3]);
        int rl = d1 + 2 * rp;
        *(float4*)(o + (size_t)rl * DH + d2)       = make_float4(u0.x, u1.x, u2.x, u3.x);
        *(float4*)(o + (size_t)(rl + 1) * DH + d2) = make_float4(u0.y, u1.y, u2.y, u3.y);
    }
}

__global__ void __launch_bounds__(512, 1)
k_grad(const float* __restrict__ w0g_all, const float* __restrict__ w1g_all,
       float* __restrict__ out) {
    extern __shared__ float sm[];
    float* ws  = sm;                        // 128*140 = 17920
    float* ks  = ws + 128 * WPITCH;         // 64*128 = 8192
    float* vs  = ks + MROWS * DH;           // v -> Gn
    float* as_ = vs + MROWS * DH;           // silu(h)
    float* ss  = as_ + MROWS * DH;          // sigma(h) -> dhn
    float* lrs = ss + MROWS * DH;           // 64

    int bh = blockIdx.x >> 5;
    int tg = blockIdx.x & 31;
    int t0 = tg * CPG;
    int tid = threadIdx.x;

    // ---- load k, v, lr, w0 ----
    const float4* kg = (const float4*)(g_k + ((size_t)(bh * NCHUNK + t0)) * (CHUNK * DH));
    const float4* vg = (const float4*)(g_v + ((size_t)(bh * NCHUNK + t0)) * (CHUNK * DH));
    for (int i = tid; i < MROWS * DH / 4; i += 512) {
        ((float4*)ks)[i] = kg[i];
        ((float4*)vs)[i] = vg[i];
    }
    if (tid < MROWS) lrs[tid] = g_lr[(bh * NCHUNK + t0) * CHUNK + tid];
    const float4* w0g4 = (const float4*)(w0g_all + (size_t)bh * DH2);
    for (int i = tid; i < 4096; i += 512) {
        int row = i >> 5, col = (i & 31) * 4;
        *(float4*)&ws[row * WPITCH + col] = w0g4[i];
    }
    __syncthreads();

    int ty = tid >> 5, tx = tid & 31;
    int c0 = ty * 4, j0 = tx * 4;
    unsigned long long acc[4][2];

    // ---- GEMM A: h = k @ w0 ; store sigma(h), silu(h) ----
    gemm64(ks, ws, c0, j0, acc);
#pragma unroll
    for (int i = 0; i < 4; i++) {
        float2 h01 = unpk2(acc[i][0]), h23 = unpk2(acc[i][1]);
        float s0 = sigf(h01.x), s1 = sigf(h01.y), s2 = sigf(h23.x), s3 = sigf(h23.y);
        *(float4*)&ss[(c0 + i) * DH + j0]  = make_float4(s0, s1, s2, s3);
        *(float4*)&as_[(c0 + i) * DH + j0] = make_float4(h01.x * s0, h01.y * s1, h23.x * s2, h23.y * s3);
    }
    __syncthreads();

    // ---- load w1 ----
    const float4* w1g4 = (const float4*)(w1g_all + (size_t)bh * DH2);
    for (int i = tid; i < 4096; i += 512) {
        int row = i >> 5, col = (i & 31) * 4;
        *(float4*)&ws[row * WPITCH + col] = w1g4[i];
    }
    __syncthreads();

    // ---- GEMM B: pred = a @ w1 ; Gn = f*(v - pred) into vs ----
    gemm64(as_, ws, c0, j0, acc);
#pragma unroll
    for (int i = 0; i < 4; i++) {
        float f = 2.f * lrs[c0 + i] * (1.f / DH);
        float2 p01 = unpk2(acc[i][0]), p23 = unpk2(acc[i][1]);
        float4 vv = *(const float4*)&vs[(c0 + i) * DH + j0];
        *(float4*)&vs[(c0 + i) * DH + j0] =
            make_float4(f * (vv.x - p01.x), f * (vv.y - p01.y),
                        f * (vv.z - p23.x), f * (vv.w - p23.y));
    }
    __syncthreads();

    // ---- load w1^T (coalesced read, scattered smem store) ----
    {
        const float* w1g = w1g_all + (size_t)bh * DH2;
        for (int i = tid; i < DH2; i += 512) {
            ws[(i & 127) * WPITCH + (i >> 7)] = w1g[i];
        }
    }
    __syncthreads();

    int d1 = (tid >> 5) * 8, d2 = (tid & 31) * 4;

    // ---- G1: s1 = a^T @ Gn per chunk (doesn't touch ws/ss) ----
#pragma unroll
    for (int ch = 0; ch < CPG; ch++) {
        float* o1 = out + ((size_t)((BH + bh) * NCHUNK + t0 + ch)) * DH2;
        outer16(as_, vs, ch * CHUNK, d1, d2, o1);
    }

    // ---- GEMM C: dA = Gn @ w1^T ; dhn = dA * (s + a*(1-s)) into ss ----
    gemm64(vs, ws, c0, j0, acc);
#pragma unroll
    for (int i = 0; i < 4; i++) {
        float2 d01 = unpk2(acc[i][0]), d23 = unpk2(acc[i][1]);
        float4 sv = *(const float4*)&ss[(c0 + i) * DH + j0];
        float4 av = *(const float4*)&as_[(c0 + i) * DH + j0];
        d01.x *= sv.x + av.x * (1.f - sv.x);
        d01.y *= sv.y + av.y * (1.f - sv.y);
        d23.x *= sv.z + av.z * (1.f - sv.z);
        d23.y *= sv.w + av.w * (1.f - sv.w);
        *(float4*)&ss[(c0 + i) * DH + j0] = make_float4(d01.x, d01.y, d23.x, d23.y);
    }
    __syncthreads();

    // ---- G0: s0 = k^T @ dhn per chunk ----
#pragma unroll
    for (int ch = 0; ch < CPG; ch++) {
        float* o0 = out + ((size_t)(bh * NCHUNK + t0 + ch)) * DH2;
        outer16(ks, ss, ch * CHUNK, d1, d2, o0);
    }
}

// ---------------- K5: fused momentum + decay scan ----------------
__global__ void k_scan(float* __restrict__ out) {
    __shared__ float moms[NCHUNK], decs[NCHUNK];
    int blk = blockIdx.x;
    int sbh = blk >> 5;
    int eb  = blk & 31;
    int bh  = sbh & 7;
    int tid = threadIdx.x;
    if (tid < NCHUNK) {
        moms[tid] = g_mom[bh * NCHUNK + tid];
        decs[tid] = 1.f - g_dec[bh * NCHUNK + tid];
    }
    __syncthreads();
    size_t base = (size_t)sbh * NCHUNK * DH2 + (size_t)eb * 512 + tid * 4;
    float4 m = make_float4(0.f, 0.f, 0.f, 0.f);
    float4 u = make_float4(0.f, 0.f, 0.f, 0.f);
#pragma unroll 4
    for (int t = 0; t < NCHUNK; t++) {
        size_t idx = base + (size_t)t * DH2;
        float4 sv = *(float4*)(out + idx);
        float mo = moms[t], de = decs[t];
        m.x = mo * m.x + sv.x;  m.y = mo * m.y + sv.y;
        m.z = mo * m.z + sv.z;  m.w = mo * m.w + sv.w;
        u.x = de * u.x + m.x;   u.y = de * u.y + m.y;
        u.z = de * u.z + m.z;   u.w = de * u.w + m.w;
        *(float4*)(out + idx) = u;
    }
}

// ---------------- launch ----------------
extern "C" void kernel_launch(void* const* d_in, const int* in_sizes, int n_in,
                              void* d_out, int out_size) {
    const float* seq   = (const float*)d_in[0];
    const float* scale = (const float*)d_in[1];
    const float* Wkv   = (const float*)d_in[2];
    const float* Wstep = (const float*)d_in[3];
    const float* Wmom  = (const float*)d_in[4];
    const float* Wdec  = (const float*)d_in[5];
    const float* w0    = (const float*)d_in[6];
    const float* w1    = (const float*)d_in[7];
    float* out = (float*)d_out;

    const int GRAD_SMEM = (128 * WPITCH + 4 * MROWS * DH + 64) * 4;  // 203008 B
    const int KV_SMEM = KV_ROWS * DIMD * 4;
    cudaFuncSetAttribute(k_grad, cudaFuncAttributeMaxDynamicSharedMemorySize, GRAD_SMEM);
    cudaFuncSetAttribute(k_kvproj, cudaFuncAttributeMaxDynamicSharedMemorySize, KV_SMEM);

    k_rmsnorm<<<BB * SS, 128>>>(seq, scale, Wstep);
    k_chunkstats<<<BB * NCHUNK, 128>>>(Wmom, Wdec);
    k_kvproj<<<512, 256, KV_SMEM>>>(Wkv);
    k_grad<<<BH * (NCHUNK / CPG), 512, GRAD_SMEM>>>(w0, w1, out);
    k_scan<<<512, 128>>>(out);
}